// round 5
// baseline (speedup 1.0000x reference)
#include <cuda_runtime.h>

#define NN 100000
#define F  64
#define EMAX 1600000
#define SCAN_BS 512
#define NBLK ((NN + SCAN_BS - 1) / SCAN_BS)   // 196
#define NCH (NN / 32)                          // 3125 chunks of 32 nodes

typedef unsigned long long ull;

// Scratch (allocation-free: __device__ globals)
__device__ __align__(16) float g_agg[(size_t)NN * F];
__device__ __align__(16) float g_x2[(size_t)NN * F];
__device__ int g_deg[NN];
__device__ int g_cur[NN];
__device__ int g_rowp[NN + 1];
__device__ int g_bsum[NBLK];
__device__ int g_csr[EMAX];

__device__ __forceinline__ ull ffma2(ull a, ull b, ull c) {
    ull d;
    asm("fma.rn.f32x2 %0, %1, %2, %3;" : "=l"(d) : "l"(a), "l"(b), "l"(c));
    return d;
}
__device__ __forceinline__ ull dup2(float x) {
    ull d;
    asm("mov.b64 %0, {%1, %1};" : "=l"(d) : "f"(x));
    return d;
}
__device__ __forceinline__ ull pack2(float lo, float hi) {
    ull d;
    asm("mov.b64 %0, {%1, %2};" : "=l"(d) : "f"(lo), "f"(hi));
    return d;
}
__device__ __forceinline__ float2 unpack2(ull v) {
    float2 r;
    asm("mov.b64 {%0, %1}, %2;" : "=f"(r.x), "=f"(r.y) : "l"(v));
    return r;
}

__global__ void zero_idx_kernel() {
    int i = blockIdx.x * blockDim.x + threadIdx.x;
    if (i < NN) { g_deg[i] = 0; g_cur[i] = 0; }
}

__global__ void hist_kernel(const int* __restrict__ dst, int E) {
    int e = blockIdx.x * blockDim.x + threadIdx.x;
    if (e >= E) return;
    int d = __ldg(&dst[e]);
    if ((unsigned)d < NN) atomicAdd(&g_deg[d], 1);
}

__global__ void scanA_kernel() {
    __shared__ int s[SCAN_BS];
    int tid = threadIdx.x;
    int gid = blockIdx.x * SCAN_BS + tid;
    int v = (gid < NN) ? g_deg[gid] : 0;
    s[tid] = v;
    __syncthreads();
    for (int off = 1; off < SCAN_BS; off <<= 1) {
        int t = (tid >= off) ? s[tid - off] : 0;
        __syncthreads();
        s[tid] += t;
        __syncthreads();
    }
    if (gid < NN) g_rowp[gid] = s[tid] - v;          // block-local exclusive
    if (tid == SCAN_BS - 1) g_bsum[blockIdx.x] = s[tid];
}

// Carry-in: each block reduces g_bsum[0..bid) inline (replaces old scanB+scanC)
__global__ void scanC_kernel(int E) {
    __shared__ int wsum[16];
    int tid = threadIdx.x, bid = blockIdx.x;
    int v = (tid < bid) ? g_bsum[tid] : 0;           // bid < 196 < 512
    #pragma unroll
    for (int o = 16; o; o >>= 1) v += __shfl_down_sync(0xffffffffu, v, o);
    if ((tid & 31) == 0) wsum[tid >> 5] = v;
    __syncthreads();
    int total = 0;
    #pragma unroll
    for (int w = 0; w < 16; w++) total += wsum[w];
    int gid = bid * SCAN_BS + tid;
    if (gid < NN) g_rowp[gid] += total;
    if (bid == 0 && tid == 0) g_rowp[NN] = E;
}

__global__ void fill_kernel(const int* __restrict__ src,
                            const int* __restrict__ dst, int E) {
    int e = blockIdx.x * blockDim.x + threadIdx.x;
    if (e >= E) return;
    int d = __ldg(&dst[e]);
    int s = __ldg(&src[e]);
    if ((unsigned)d >= NN || (unsigned)s >= NN) return;
    int pos = atomicAdd(&g_cur[d], 1);
    g_csr[g_rowp[d] + pos] = s;
}

// CSR mean aggregation: 16 threads/node, float4 slices, 4-deep MLP unroll.
__global__ void agg_kernel(const float4* __restrict__ x4,
                           float4* __restrict__ out4) {
    int t = blockIdx.x * blockDim.x + threadIdx.x;
    int node = t >> 4;
    int sub = t & 15;
    if (node >= NN) return;
    int beg = g_rowp[node];
    int end = g_rowp[node + 1];
    float4 a = make_float4(0.f, 0.f, 0.f, 0.f);
    float4 b = make_float4(0.f, 0.f, 0.f, 0.f);
    int i = beg;
    for (; i + 4 <= end; i += 4) {
        int s0 = __ldg(&g_csr[i]);
        int s1 = __ldg(&g_csr[i + 1]);
        int s2 = __ldg(&g_csr[i + 2]);
        int s3 = __ldg(&g_csr[i + 3]);
        float4 v0 = __ldg(&x4[(size_t)s0 * 16 + sub]);
        float4 v1 = __ldg(&x4[(size_t)s1 * 16 + sub]);
        float4 v2 = __ldg(&x4[(size_t)s2 * 16 + sub]);
        float4 v3 = __ldg(&x4[(size_t)s3 * 16 + sub]);
        a.x += v0.x + v1.x; a.y += v0.y + v1.y;
        a.z += v0.z + v1.z; a.w += v0.w + v1.w;
        b.x += v2.x + v3.x; b.y += v2.y + v3.y;
        b.z += v2.z + v3.z; b.w += v2.w + v3.w;
    }
    for (; i < end; i++) {
        int s0 = __ldg(&g_csr[i]);
        float4 v0 = __ldg(&x4[(size_t)s0 * 16 + sub]);
        a.x += v0.x; a.y += v0.y; a.z += v0.z; a.w += v0.w;
    }
    float inv = 1.0f / (float)max(end - beg, 1);
    out4[(size_t)node * 16 + sub] =
        make_float4((a.x + b.x) * inv, (a.y + b.y) * inv,
                    (a.z + b.z) * inv, (a.w + b.w) * inv);
}

// Fused layer with packed f32x2 FMA, 2 nodes per 64-bit lane.
// Block: 64 j-threads x 4 groups; each group owns 8 nodes (4 pairs); chunk = 32 nodes.
template <bool RELU2>
__global__ void __launch_bounds__(256, 2)
fused_layer(const float* __restrict__ xin,
            const float* __restrict__ Wl,
            const float* __restrict__ bl,
            const float* __restrict__ Wr,
            const float* __restrict__ W2,
            const float* __restrict__ b2,
            float* __restrict__ out) {
    extern __shared__ char smraw[];
    float* sWl = (float*)smraw;            // 16KB
    float* sWr = sWl + F * F;              // 16KB
    float* sW2 = sWr + F * F;              // 16KB
    ull* sMp = (ull*)(sW2 + F * F);        // 16 pairs x 64 k = 8KB
    ull* sHp = sMp + 16 * F;               // 8KB
    ull* sTp = sHp + 16 * F;               // 8KB  (total 72KB)

    int j = threadIdx.x, g = threadIdx.y;
    int tid = g * 64 + j;
    for (int i = tid; i < F * F; i += 256) {
        sWl[i] = Wl[i]; sWr[i] = Wr[i]; sW2[i] = W2[i];
    }
    float blj = bl[j];
    float b2j = b2[j];

    const ulonglong2* mp2 = (const ulonglong2*)sMp;
    const ulonglong2* hp2 = (const ulonglong2*)sHp;
    const ulonglong2* tp2 = (const ulonglong2*)sTp;

    for (int chunk = blockIdx.x; chunk < NCH; chunk += gridDim.x) {
        __syncthreads();
        int base8 = chunk * 32 + g * 8;
        // Stage nodes as packed pairs: sMp[pair*64 + j] = (node2q, node2q+1)
        #pragma unroll
        for (int q = 0; q < 4; q++) {
            int n0 = base8 + 2 * q;
            int pr = g * 4 + q;
            float m0 = g_agg[(size_t)n0 * F + j];
            float m1 = g_agg[(size_t)(n0 + 1) * F + j];
            float h0 = xin[(size_t)n0 * F + j];
            float h1 = xin[(size_t)(n0 + 1) * F + j];
            sMp[pr * F + j] = pack2(m0, m1);
            sHp[pr * F + j] = pack2(h0, h1);
        }
        __syncthreads();
        // Stage 1: sage = mean@Wl + x@Wr + bl, relu
        ull acc[4];
        #pragma unroll
        for (int p = 0; p < 4; p++) acc[p] = dup2(blj);
        #pragma unroll 8
        for (int k2 = 0; k2 < F / 2; k2++) {
            int k = 2 * k2;
            ull wl0 = dup2(sWl[k * F + j]);
            ull wl1 = dup2(sWl[(k + 1) * F + j]);
            ull wr0 = dup2(sWr[k * F + j]);
            ull wr1 = dup2(sWr[(k + 1) * F + j]);
            #pragma unroll
            for (int p = 0; p < 4; p++) {
                ulonglong2 m = mp2[(g * 4 + p) * (F / 2) + k2];
                ulonglong2 h = hp2[(g * 4 + p) * (F / 2) + k2];
                acc[p] = ffma2(m.x, wl0, acc[p]);
                acc[p] = ffma2(m.y, wl1, acc[p]);
                acc[p] = ffma2(h.x, wr0, acc[p]);
                acc[p] = ffma2(h.y, wr1, acc[p]);
            }
        }
        #pragma unroll
        for (int p = 0; p < 4; p++) {
            float2 t = unpack2(acc[p]);
            sTp[(g * 4 + p) * F + j] = pack2(fmaxf(t.x, 0.f), fmaxf(t.y, 0.f));
        }
        __syncthreads();
        // Stage 2: @W2 + b2
        ull a2[4];
        #pragma unroll
        for (int p = 0; p < 4; p++) a2[p] = dup2(b2j);
        #pragma unroll 8
        for (int k2 = 0; k2 < F / 2; k2++) {
            int k = 2 * k2;
            ull w0 = dup2(sW2[k * F + j]);
            ull w1 = dup2(sW2[(k + 1) * F + j]);
            #pragma unroll
            for (int p = 0; p < 4; p++) {
                ulonglong2 t = tp2[(g * 4 + p) * (F / 2) + k2];
                a2[p] = ffma2(t.x, w0, a2[p]);
                a2[p] = ffma2(t.y, w1, a2[p]);
            }
        }
        #pragma unroll
        for (int p = 0; p < 4; p++) {
            float2 v = unpack2(a2[p]);
            int n0 = base8 + 2 * p;
            if (RELU2) { v.x = fmaxf(v.x, 0.f); v.y = fmaxf(v.y, 0.f); }
            out[(size_t)n0 * F + j] = v.x;
            out[(size_t)(n0 + 1) * F + j] = v.y;
        }
    }
}

#define FUSED_SMEM (48 * 1024 + 24 * 1024)

extern "C" void kernel_launch(void* const* d_in, const int* in_sizes, int n_in,
                              void* d_out, int out_size) {
    const float* h   = (const float*)d_in[0];
    const int*   ei  = (const int*)d_in[1];
    const float* w1l = (const float*)d_in[2];
    const float* b1l = (const float*)d_in[3];
    const float* w1r = (const float*)d_in[4];
    const float* wl1 = (const float*)d_in[5];
    const float* bl1 = (const float*)d_in[6];
    const float* w2l = (const float*)d_in[7];
    const float* b2l = (const float*)d_in[8];
    const float* w2r = (const float*)d_in[9];
    const float* wl2 = (const float*)d_in[10];
    const float* bl2 = (const float*)d_in[11];
    float* out = (float*)d_out;

    int E = in_sizes[1] / 2;
    if (E > EMAX) E = EMAX;
    const int* src = ei;
    const int* dst = ei + E;

    void *p_agg = nullptr, *p_x2 = nullptr;
    cudaGetSymbolAddress(&p_agg, g_agg);
    cudaGetSymbolAddress(&p_x2, g_x2);
    float* agg = (float*)p_agg;
    float* x2  = (float*)p_x2;

    static bool attr_set = false;
    if (!attr_set) {
        cudaFuncSetAttribute(fused_layer<true>,
                             cudaFuncAttributeMaxDynamicSharedMemorySize, FUSED_SMEM);
        cudaFuncSetAttribute(fused_layer<false>,
                             cudaFuncAttributeMaxDynamicSharedMemorySize, FUSED_SMEM);
        attr_set = true;
    }

    int eb = (E + 255) / 256;
    dim3 nb(64, 4);

    // CSR build
    zero_idx_kernel<<<(NN + 255) / 256, 256>>>();
    hist_kernel<<<eb, 256>>>(dst, E);
    scanA_kernel<<<NBLK, SCAN_BS>>>();
    scanC_kernel<<<NBLK, SCAN_BS>>>(E);
    fill_kernel<<<eb, 256>>>(src, dst, E);

    // Layer 1
    agg_kernel<<<(NN * 16 + 255) / 256, 256>>>((const float4*)h, (float4*)agg);
    fused_layer<true><<<592, nb, FUSED_SMEM>>>(h, w1l, b1l, w1r, wl1, bl1, x2);
    // Layer 2
    agg_kernel<<<(NN * 16 + 255) / 256, 256>>>((const float4*)x2, (float4*)agg);
    fused_layer<false><<<592, nb, FUSED_SMEM>>>(x2, w2l, b2l, w2r, wl2, bl2, out);
}

// round 6
// speedup vs baseline: 1.5328x; 1.5328x over previous
#include <cuda_runtime.h>

#define NN 100000
#define F  64
#define EMAX 1600000
#define SCAN_BS 512
#define NBLK ((NN + SCAN_BS - 1) / SCAN_BS)   // 196
#define NCH (NN / 32)                          // 3125 chunks of 32 nodes

typedef unsigned long long ull;

// Scratch (allocation-free: __device__ globals)
__device__ __align__(16) float g_agg[(size_t)NN * F];
__device__ __align__(16) float g_x2[(size_t)NN * F];
__device__ int g_deg[NN];
__device__ int g_cur[NN];
__device__ int g_rowp[NN + 1];
__device__ int g_bsum[NBLK];
__device__ int g_csr[EMAX];

__device__ __forceinline__ ull ffma2(ull a, ull b, ull c) {
    ull d;
    asm("fma.rn.f32x2 %0, %1, %2, %3;" : "=l"(d) : "l"(a), "l"(b), "l"(c));
    return d;
}
__device__ __forceinline__ ull dup2(float x) {
    ull d;
    asm("mov.b64 %0, {%1, %1};" : "=l"(d) : "f"(x));
    return d;
}
__device__ __forceinline__ ull pack2(float lo, float hi) {
    ull d;
    asm("mov.b64 %0, {%1, %2};" : "=l"(d) : "f"(lo), "f"(hi));
    return d;
}
__device__ __forceinline__ float2 unpack2(ull v) {
    float2 r;
    asm("mov.b64 {%0, %1}, %2;" : "=f"(r.x), "=f"(r.y) : "l"(v));
    return r;
}

__global__ void zero_idx_kernel() {
    int i = blockIdx.x * blockDim.x + threadIdx.x;
    if (i < NN) { g_deg[i] = 0; g_cur[i] = 0; }
}

__global__ void hist_kernel(const int* __restrict__ dst, int E) {
    int e = blockIdx.x * blockDim.x + threadIdx.x;
    if (e >= E) return;
    int d = __ldg(&dst[e]);
    if ((unsigned)d < NN) atomicAdd(&g_deg[d], 1);
}

__global__ void scanA_kernel() {
    __shared__ int s[SCAN_BS];
    int tid = threadIdx.x;
    int gid = blockIdx.x * SCAN_BS + tid;
    int v = (gid < NN) ? g_deg[gid] : 0;
    s[tid] = v;
    __syncthreads();
    for (int off = 1; off < SCAN_BS; off <<= 1) {
        int t = (tid >= off) ? s[tid - off] : 0;
        __syncthreads();
        s[tid] += t;
        __syncthreads();
    }
    if (gid < NN) g_rowp[gid] = s[tid] - v;          // block-local exclusive
    if (tid == SCAN_BS - 1) g_bsum[blockIdx.x] = s[tid];
}

// Carry-in: each block reduces g_bsum[0..bid) inline
__global__ void scanC_kernel(int E) {
    __shared__ int wsum[16];
    int tid = threadIdx.x, bid = blockIdx.x;
    int v = (tid < bid) ? g_bsum[tid] : 0;           // bid < 196 < 512
    #pragma unroll
    for (int o = 16; o; o >>= 1) v += __shfl_down_sync(0xffffffffu, v, o);
    if ((tid & 31) == 0) wsum[tid >> 5] = v;
    __syncthreads();
    int total = 0;
    #pragma unroll
    for (int w = 0; w < 16; w++) total += wsum[w];
    int gid = bid * SCAN_BS + tid;
    if (gid < NN) g_rowp[gid] += total;
    if (bid == 0 && tid == 0) g_rowp[NN] = E;
}

__global__ void fill_kernel(const int* __restrict__ src,
                            const int* __restrict__ dst, int E) {
    int e = blockIdx.x * blockDim.x + threadIdx.x;
    if (e >= E) return;
    int d = __ldg(&dst[e]);
    int s = __ldg(&src[e]);
    if ((unsigned)d >= NN || (unsigned)s >= NN) return;
    int pos = atomicAdd(&g_cur[d], 1);
    g_csr[g_rowp[d] + pos] = s;
}

// CSR mean aggregation: 16 threads/node, float4 slices, 4-deep MLP unroll.
__global__ void agg_kernel(const float4* __restrict__ x4,
                           float4* __restrict__ out4) {
    int t = blockIdx.x * blockDim.x + threadIdx.x;
    int node = t >> 4;
    int sub = t & 15;
    if (node >= NN) return;
    int beg = g_rowp[node];
    int end = g_rowp[node + 1];
    float4 a = make_float4(0.f, 0.f, 0.f, 0.f);
    float4 b = make_float4(0.f, 0.f, 0.f, 0.f);
    int i = beg;
    for (; i + 4 <= end; i += 4) {
        int s0 = __ldg(&g_csr[i]);
        int s1 = __ldg(&g_csr[i + 1]);
        int s2 = __ldg(&g_csr[i + 2]);
        int s3 = __ldg(&g_csr[i + 3]);
        float4 v0 = __ldg(&x4[(size_t)s0 * 16 + sub]);
        float4 v1 = __ldg(&x4[(size_t)s1 * 16 + sub]);
        float4 v2 = __ldg(&x4[(size_t)s2 * 16 + sub]);
        float4 v3 = __ldg(&x4[(size_t)s3 * 16 + sub]);
        a.x += v0.x + v1.x; a.y += v0.y + v1.y;
        a.z += v0.z + v1.z; a.w += v0.w + v1.w;
        b.x += v2.x + v3.x; b.y += v2.y + v3.y;
        b.z += v2.z + v3.z; b.w += v2.w + v3.w;
    }
    for (; i < end; i++) {
        int s0 = __ldg(&g_csr[i]);
        float4 v0 = __ldg(&x4[(size_t)s0 * 16 + sub]);
        a.x += v0.x; a.y += v0.y; a.z += v0.z; a.w += v0.w;
    }
    float inv = 1.0f / (float)max(end - beg, 1);
    out4[(size_t)node * 16 + sub] =
        make_float4((a.x + b.x) * inv, (a.y + b.y) * inv,
                    (a.z + b.z) * inv, (a.w + b.w) * inv);
}

// Fused layer with packed f32x2 FMA, 2 nodes per 64-bit lane.
// Block: 64 j-threads x 4 groups; each group owns 8 nodes (4 pairs); chunk = 32 nodes.
// Unroll kept LOW to avoid register spills (R4 post-mortem).
template <bool RELU2>
__global__ void __launch_bounds__(256, 2)
fused_layer(const float* __restrict__ xin,
            const float* __restrict__ Wl,
            const float* __restrict__ bl,
            const float* __restrict__ Wr,
            const float* __restrict__ W2,
            const float* __restrict__ b2,
            float* __restrict__ out) {
    extern __shared__ char smraw[];
    float* sWl = (float*)smraw;            // 16KB
    float* sWr = sWl + F * F;              // 16KB
    float* sW2 = sWr + F * F;              // 16KB
    ull* sMp = (ull*)(sW2 + F * F);        // 16 pairs x 64 k = 8KB
    ull* sHp = sMp + 16 * F;               // 8KB
    ull* sTp = sHp + 16 * F;               // 8KB  (total 72KB)

    int j = threadIdx.x, g = threadIdx.y;
    int tid = g * 64 + j;
    for (int i = tid; i < F * F; i += 256) {
        sWl[i] = Wl[i]; sWr[i] = Wr[i]; sW2[i] = W2[i];
    }
    float blj = bl[j];
    float b2j = b2[j];

    const ulonglong2* mp2 = (const ulonglong2*)sMp;
    const ulonglong2* hp2 = (const ulonglong2*)sHp;
    const ulonglong2* tp2 = (const ulonglong2*)sTp;

    for (int chunk = blockIdx.x; chunk < NCH; chunk += gridDim.x) {
        __syncthreads();
        int base8 = chunk * 32 + g * 8;
        // Stage nodes as packed pairs: sMp[pair*64 + j] = (node2q, node2q+1)
        #pragma unroll
        for (int q = 0; q < 4; q++) {
            int n0 = base8 + 2 * q;
            int pr = g * 4 + q;
            sMp[pr * F + j] = pack2(g_agg[(size_t)n0 * F + j],
                                    g_agg[(size_t)(n0 + 1) * F + j]);
            sHp[pr * F + j] = pack2(xin[(size_t)n0 * F + j],
                                    xin[(size_t)(n0 + 1) * F + j]);
        }
        __syncthreads();
        // Stage 1: sage = mean@Wl + x@Wr + bl, relu
        ull acc0 = dup2(blj), acc1 = acc0, acc2 = acc0, acc3 = acc0;
        #pragma unroll 2
        for (int k2 = 0; k2 < F / 2; k2++) {
            int k = 2 * k2;
            ull wl0 = dup2(sWl[k * F + j]);
            ull wl1 = dup2(sWl[(k + 1) * F + j]);
            ull wr0 = dup2(sWr[k * F + j]);
            ull wr1 = dup2(sWr[(k + 1) * F + j]);
            {
                ulonglong2 m = mp2[(g * 4 + 0) * (F / 2) + k2];
                ulonglong2 h = hp2[(g * 4 + 0) * (F / 2) + k2];
                acc0 = ffma2(m.x, wl0, acc0); acc0 = ffma2(m.y, wl1, acc0);
                acc0 = ffma2(h.x, wr0, acc0); acc0 = ffma2(h.y, wr1, acc0);
            }
            {
                ulonglong2 m = mp2[(g * 4 + 1) * (F / 2) + k2];
                ulonglong2 h = hp2[(g * 4 + 1) * (F / 2) + k2];
                acc1 = ffma2(m.x, wl0, acc1); acc1 = ffma2(m.y, wl1, acc1);
                acc1 = ffma2(h.x, wr0, acc1); acc1 = ffma2(h.y, wr1, acc1);
            }
            {
                ulonglong2 m = mp2[(g * 4 + 2) * (F / 2) + k2];
                ulonglong2 h = hp2[(g * 4 + 2) * (F / 2) + k2];
                acc2 = ffma2(m.x, wl0, acc2); acc2 = ffma2(m.y, wl1, acc2);
                acc2 = ffma2(h.x, wr0, acc2); acc2 = ffma2(h.y, wr1, acc2);
            }
            {
                ulonglong2 m = mp2[(g * 4 + 3) * (F / 2) + k2];
                ulonglong2 h = hp2[(g * 4 + 3) * (F / 2) + k2];
                acc3 = ffma2(m.x, wl0, acc3); acc3 = ffma2(m.y, wl1, acc3);
                acc3 = ffma2(h.x, wr0, acc3); acc3 = ffma2(h.y, wr1, acc3);
            }
        }
        {
            float2 t0 = unpack2(acc0), t1 = unpack2(acc1);
            float2 t2 = unpack2(acc2), t3 = unpack2(acc3);
            sTp[(g * 4 + 0) * F + j] = pack2(fmaxf(t0.x, 0.f), fmaxf(t0.y, 0.f));
            sTp[(g * 4 + 1) * F + j] = pack2(fmaxf(t1.x, 0.f), fmaxf(t1.y, 0.f));
            sTp[(g * 4 + 2) * F + j] = pack2(fmaxf(t2.x, 0.f), fmaxf(t2.y, 0.f));
            sTp[(g * 4 + 3) * F + j] = pack2(fmaxf(t3.x, 0.f), fmaxf(t3.y, 0.f));
        }
        __syncthreads();
        // Stage 2: @W2 + b2
        ull a0 = dup2(b2j), a1 = a0, a2 = a0, a3 = a0;
        #pragma unroll 2
        for (int k2 = 0; k2 < F / 2; k2++) {
            int k = 2 * k2;
            ull w0 = dup2(sW2[k * F + j]);
            ull w1 = dup2(sW2[(k + 1) * F + j]);
            {
                ulonglong2 t = tp2[(g * 4 + 0) * (F / 2) + k2];
                a0 = ffma2(t.x, w0, a0); a0 = ffma2(t.y, w1, a0);
            }
            {
                ulonglong2 t = tp2[(g * 4 + 1) * (F / 2) + k2];
                a1 = ffma2(t.x, w0, a1); a1 = ffma2(t.y, w1, a1);
            }
            {
                ulonglong2 t = tp2[(g * 4 + 2) * (F / 2) + k2];
                a2 = ffma2(t.x, w0, a2); a2 = ffma2(t.y, w1, a2);
            }
            {
                ulonglong2 t = tp2[(g * 4 + 3) * (F / 2) + k2];
                a3 = ffma2(t.x, w0, a3); a3 = ffma2(t.y, w1, a3);
            }
        }
        #pragma unroll
        for (int p = 0; p < 4; p++) {
            ull av = (p == 0) ? a0 : (p == 1) ? a1 : (p == 2) ? a2 : a3;
            float2 v = unpack2(av);
            int n0 = base8 + 2 * p;
            if (RELU2) { v.x = fmaxf(v.x, 0.f); v.y = fmaxf(v.y, 0.f); }
            out[(size_t)n0 * F + j] = v.x;
            out[(size_t)(n0 + 1) * F + j] = v.y;
        }
    }
}

#define FUSED_SMEM (48 * 1024 + 24 * 1024)

extern "C" void kernel_launch(void* const* d_in, const int* in_sizes, int n_in,
                              void* d_out, int out_size) {
    const float* h   = (const float*)d_in[0];
    const int*   ei  = (const int*)d_in[1];
    const float* w1l = (const float*)d_in[2];
    const float* b1l = (const float*)d_in[3];
    const float* w1r = (const float*)d_in[4];
    const float* wl1 = (const float*)d_in[5];
    const float* bl1 = (const float*)d_in[6];
    const float* w2l = (const float*)d_in[7];
    const float* b2l = (const float*)d_in[8];
    const float* w2r = (const float*)d_in[9];
    const float* wl2 = (const float*)d_in[10];
    const float* bl2 = (const float*)d_in[11];
    float* out = (float*)d_out;

    int E = in_sizes[1] / 2;
    if (E > EMAX) E = EMAX;
    const int* src = ei;
    const int* dst = ei + E;

    void *p_agg = nullptr, *p_x2 = nullptr;
    cudaGetSymbolAddress(&p_agg, g_agg);
    cudaGetSymbolAddress(&p_x2, g_x2);
    float* agg = (float*)p_agg;
    float* x2  = (float*)p_x2;

    static bool attr_set = false;
    if (!attr_set) {
        cudaFuncSetAttribute(fused_layer<true>,
                             cudaFuncAttributeMaxDynamicSharedMemorySize, FUSED_SMEM);
        cudaFuncSetAttribute(fused_layer<false>,
                             cudaFuncAttributeMaxDynamicSharedMemorySize, FUSED_SMEM);
        attr_set = true;
    }

    int eb = (E + 255) / 256;
    dim3 nb(64, 4);

    // CSR build
    zero_idx_kernel<<<(NN + 255) / 256, 256>>>();
    hist_kernel<<<eb, 256>>>(dst, E);
    scanA_kernel<<<NBLK, SCAN_BS>>>();
    scanC_kernel<<<NBLK, SCAN_BS>>>(E);
    fill_kernel<<<eb, 256>>>(src, dst, E);

    // Layer 1
    agg_kernel<<<(NN * 16 + 255) / 256, 256>>>((const float4*)h, (float4*)agg);
    fused_layer<true><<<592, nb, FUSED_SMEM>>>(h, w1l, b1l, w1r, wl1, bl1, x2);
    // Layer 2
    agg_kernel<<<(NN * 16 + 255) / 256, 256>>>((const float4*)x2, (float4*)agg);
    fused_layer<false><<<592, nb, FUSED_SMEM>>>(x2, w2l, b2l, w2r, wl2, bl2, out);
}